// round 3
// baseline (speedup 1.0000x reference)
#include <cuda_runtime.h>
#include <cuda_bf16.h>

#define N_NODES 100000
#define E_EDGES 1600000
#define D 64
#define NBLK 98                    // ceil(N_NODES / 1024)

// CSR scratch
__device__ int g_hist[3][N_NODES];        // per-etype in-degree
__device__ int g_scan[3][N_NODES];        // block-local inclusive scan
__device__ int g_bsum[3][NBLK];           // per-block totals
__device__ int g_bbase[3][NBLK];          // exclusive base per block
__device__ int g_cursor[3][N_NODES];      // start -> (after scatter) end
__device__ int g_bucket[3][E_EDGES];      // src ids grouped by dst

// ---------------------------------------------------------------------------
__global__ __launch_bounds__(256) void k_zero_hist() {
    int idx = blockIdx.x * blockDim.x + threadIdx.x;
    int stride = gridDim.x * blockDim.x;
    int4* h = reinterpret_cast<int4*>(&g_hist[0][0]);
    const int n4 = 3 * N_NODES / 4;
    int4 z = make_int4(0, 0, 0, 0);
    for (int i = idx; i < n4; i += stride) h[i] = z;
}

// ---------------------------------------------------------------------------
__global__ __launch_bounds__(256) void k_hist(
    const int* __restrict__ d0, const int* __restrict__ d1,
    const int* __restrict__ d2)
{
    int e = blockIdx.y;
    const int* __restrict__ dst = (e == 0) ? d0 : (e == 1) ? d1 : d2;
    int* hist = g_hist[e];
    int idx = blockIdx.x * blockDim.x + threadIdx.x;
    int stride = gridDim.x * blockDim.x;
    for (int i = idx; i < E_EDGES; i += stride)
        atomicAdd(hist + __ldg(&dst[i]), 1);
}

// ---------------------------------------------------------------------------
// Block-level inclusive scan of 1024 counts; emit block totals.
__global__ __launch_bounds__(1024) void k_blockscan() {
    __shared__ int wsum[32];
    int e = blockIdx.y;
    int n = blockIdx.x * 1024 + threadIdx.x;
    int lane = threadIdx.x & 31;
    int wid  = threadIdx.x >> 5;

    int v = (n < N_NODES) ? g_hist[e][n] : 0;
    int sc = v;
    #pragma unroll
    for (int d = 1; d < 32; d <<= 1) {
        int t = __shfl_up_sync(0xffffffffu, sc, d);
        if (lane >= d) sc += t;
    }
    if (lane == 31) wsum[wid] = sc;
    __syncthreads();
    if (wid == 0) {
        int s = wsum[lane];
        #pragma unroll
        for (int d = 1; d < 32; d <<= 1) {
            int t = __shfl_up_sync(0xffffffffu, s, d);
            if (lane >= d) s += t;
        }
        wsum[lane] = s;
    }
    __syncthreads();
    int inc = sc + (wid > 0 ? wsum[wid - 1] : 0);
    if (n < N_NODES) g_scan[e][n] = inc;
    if (threadIdx.x == 1023) g_bsum[e][blockIdx.x] = inc;
}

// Scan the NBLK block totals (tiny) -> exclusive bases.
__global__ void k_scansums() {
    int e = blockIdx.x;
    if (threadIdx.x == 0) {
        int acc = 0;
        for (int b = 0; b < NBLK; b++) {
            g_bbase[e][b] = acc;
            acc += g_bsum[e][b];
        }
    }
}

// cursor[n] = exclusive start offset of node n's bucket.
__global__ __launch_bounds__(256) void k_addback() {
    int e = blockIdx.y;
    int n = blockIdx.x * blockDim.x + threadIdx.x;
    if (n < N_NODES)
        g_cursor[e][n] = g_scan[e][n] - g_hist[e][n] + g_bbase[e][n >> 10];
}

// ---------------------------------------------------------------------------
__global__ __launch_bounds__(256) void k_scatter(
    const int* __restrict__ s0, const int* __restrict__ d0,
    const int* __restrict__ s1, const int* __restrict__ d1,
    const int* __restrict__ s2, const int* __restrict__ d2)
{
    int e = blockIdx.y;
    const int* __restrict__ src = (e == 0) ? s0 : (e == 1) ? s1 : s2;
    const int* __restrict__ dst = (e == 0) ? d0 : (e == 1) ? d1 : d2;
    int* cursor = g_cursor[e];
    int* bucket = g_bucket[e];
    int idx = blockIdx.x * blockDim.x + threadIdx.x;
    int stride = gridDim.x * blockDim.x;
    for (int i = idx; i < E_EDGES; i += stride) {
        int d = __ldg(&dst[i]);
        int pos = atomicAdd(cursor + d, 1);
        bucket[pos] = __ldg(&src[i]);
    }
}

// ---------------------------------------------------------------------------
// Fused gather + mean + GEMM + bias. One warp per node (grid-stride).
// After k_scatter, g_cursor[e][n] == end of node n's bucket; begin = end-cnt.
// ---------------------------------------------------------------------------
__global__ __launch_bounds__(256) void k_fused(
    const float* __restrict__ x,
    const float* __restrict__ W0, const float* __restrict__ b0,
    const float* __restrict__ W1, const float* __restrict__ b1,
    const float* __restrict__ W2, const float* __restrict__ b2,
    float* __restrict__ out)
{
    extern __shared__ float sm[];
    float* Wsh  = sm;                 // 3*4096
    float* bsh  = sm + 12288;         // 192
    float* mbuf = sm + 12480;         // 8 warps * 64

    int tid  = threadIdx.x;
    int lane = tid & 31;
    int wid  = tid >> 5;
    float* mb = mbuf + wid * 64;

    for (int i = tid; i < 4096; i += 256) {
        Wsh[i]        = W0[i];
        Wsh[4096 + i] = W1[i];
        Wsh[8192 + i] = W2[i];
    }
    if (tid < 64) {
        bsh[tid]       = b0[tid];
        bsh[64 + tid]  = b1[tid];
        bsh[128 + tid] = b2[tid];
    }
    __syncthreads();

    int gw = blockIdx.x * 8 + wid;
    int nwarps = gridDim.x * 8;
    int c = 2 * lane;

    for (int n = gw; n < N_NODES; n += nwarps) {
        float o0 = 0.f, o1 = 0.f;

        #pragma unroll
        for (int e = 0; e < 3; e++) {
            int end = g_cursor[e][n];
            int cnt = g_hist[e][n];
            if (cnt == 0) continue;
            int beg = end - cnt;
            const int* __restrict__ bucket = g_bucket[e];

            float a0 = 0.f, a1 = 0.f;
            int i = beg;
            // full chunks of 32 edges
            for (; i + 32 <= end; i += 32) {
                int myid = bucket[i + lane];
                #pragma unroll 8
                for (int j = 0; j < 32; j++) {
                    int s = __shfl_sync(0xffffffffu, myid, j);
                    float2 v = *reinterpret_cast<const float2*>(x + s * 64 + c);
                    a0 += v.x; a1 += v.y;
                }
            }
            // tail
            if (i < end) {
                int m = end - i;
                int myid = (i + lane < end) ? bucket[i + lane] : 0;
                for (int j = 0; j < m; j++) {
                    int s = __shfl_sync(0xffffffffu, myid, j);
                    float2 v = *reinterpret_cast<const float2*>(x + s * 64 + c);
                    a0 += v.x; a1 += v.y;
                }
            }

            float inv = 1.0f / (float)cnt;
            mb[c]     = a0 * inv;
            mb[c + 1] = a1 * inv;
            __syncwarp();

            const float* We = Wsh + e * 4096 + c;
            #pragma unroll 16
            for (int k = 0; k < 64; k++) {
                float mk = mb[k];
                float2 w = *reinterpret_cast<const float2*>(We + k * 64);
                o0 += mk * w.x;
                o1 += mk * w.y;
            }
            o0 += bsh[e * 64 + c];
            o1 += bsh[e * 64 + c + 1];
            __syncwarp();   // mbuf reuse
        }

        *reinterpret_cast<float2*>(out + n * 64 + c) = make_float2(o0, o1);
    }
}

// ---------------------------------------------------------------------------
extern "C" void kernel_launch(void* const* d_in, const int* in_sizes, int n_in,
                              void* d_out, int out_size)
{
    const float* x  = (const float*)d_in[0];
    const float* W0 = (const float*)d_in[1];
    const float* b0 = (const float*)d_in[2];
    const int*   s0 = (const int*)  d_in[3];
    const int*   t0 = (const int*)  d_in[4];
    const float* W1 = (const float*)d_in[5];
    const float* b1 = (const float*)d_in[6];
    const int*   s1 = (const int*)  d_in[7];
    const int*   t1 = (const int*)  d_in[8];
    const float* W2 = (const float*)d_in[9];
    const float* b2 = (const float*)d_in[10];
    const int*   s2 = (const int*)  d_in[11];
    const int*   t2 = (const int*)  d_in[12];
    float* out = (float*)d_out;

    k_zero_hist<<<256, 256>>>();

    dim3 gE(1184, 3);
    k_hist<<<gE, 256>>>(t0, t1, t2);

    dim3 gS(NBLK, 3);
    k_blockscan<<<gS, 1024>>>();
    k_scansums<<<3, 32>>>();

    dim3 gA((N_NODES + 255) / 256, 3);
    k_addback<<<gA, 256>>>();

    k_scatter<<<gE, 256>>>(s0, t0, s1, t1, s2, t2);

    cudaFuncSetAttribute(k_fused,
                         cudaFuncAttributeMaxDynamicSharedMemorySize, 53000);
    k_fused<<<1184, 256, 12992 * sizeof(float)>>>(x, W0, b0, W1, b1, W2, b2, out);
}